// round 3
// baseline (speedup 1.0000x reference)
#include <cuda_runtime.h>

#define B_ 32
#define S_ 2048
#define D_ 1024
#define E_ 64
#define K_ 8
#define T_ 128       // N_TAGS
#define NSPLIT 8
#define KCHUNK (D_ / NSPLIT)   // 128
#define BK 32
#define BM 64

// Scratch (allocation-free rule: __device__ globals)
__device__ float g_wt[D_ * T_];                  // 512 KB fc_w transposed [D][T]
__device__ float g_part[NSPLIT * B_ * E_ * T_];  // 8 MB k-split partials

// ---- packed f32x2 helpers (sm_103a) --------------------------------------
__device__ __forceinline__ unsigned long long pack2(float a) {
    unsigned long long r;
    asm("mov.b64 %0, {%1, %1};" : "=l"(r) : "f"(a));
    return r;
}
__device__ __forceinline__ void ffma2(unsigned long long& d,
                                      unsigned long long a,
                                      unsigned long long b) {
    asm("fma.rn.f32x2 %0, %1, %2, %3;" : "=l"(d) : "l"(a), "l"(b), "l"(d));
}

// ---------------------------------------------------------------------------
// Kernel T: transpose fc_w [T,D] -> g_wt [D,T].
// ---------------------------------------------------------------------------
__global__ __launch_bounds__(256) void transpose_kernel(const float* __restrict__ W)
{
    __shared__ float tile[32][33];
    int bx = blockIdx.x;   // over D: 32
    int by = blockIdx.y;   // over T: 4
    int x = threadIdx.x;   // 32
    int y = threadIdx.y;   // 8
    #pragma unroll
    for (int j = 0; j < 4; ++j)
        tile[y + j * 8][x] = W[(size_t)(by * 32 + y + j * 8) * D_ + bx * 32 + x];
    __syncthreads();
    #pragma unroll
    for (int j = 0; j < 4; ++j)
        g_wt[(size_t)(bx * 32 + y + j * 8) * T_ + by * 32 + x] = tile[x][y + j * 8];
}

// ---------------------------------------------------------------------------
// Fused gather+pool+GEMM (k-split partials).
// grid = (B_=32 m-blocks, NSPLIT=8), block = 256 threads.
// Stage 1: gather 64 entities x 128-k slice into swizzled sA with mean-pool.
// Stage 2: f32x2 GEMM vs g_wt tile, per-thread 4 rows x 8 cols.
// ---------------------------------------------------------------------------
__global__ __launch_bounds__(256) void gemm_fused(
    const float* __restrict__ hs,      // [B,S,D]
    const int*   __restrict__ idx,     // [B,E,K]
    const int*   __restrict__ counts,  // [B,E]
    const int*   __restrict__ nent)    // [B]
{
    __shared__ __align__(16) float sA[BM * KCHUNK];  // 32 KB, XOR-swizzled
    __shared__ __align__(16) float sW[BK][T_];       // 16 KB

    int tid   = threadIdx.x;
    int b     = blockIdx.x;            // m-block == batch (BM == E_)
    int split = blockIdx.y;
    int k0base = split * KCHUNK;

    // ---- Stage 1: gather + mean pool into sA ----
    {
        int r    = tid >> 2;           // entity row 0..63
        int part = tid & 3;            // 32-float chunk within 128-k slice
        int be   = b * E_ + r;
        int ne   = nent[b];

        float4 a[8];
        #pragma unroll
        for (int j = 0; j < 8; ++j) a[j] = make_float4(0.f, 0.f, 0.f, 0.f);

        if (r < ne) {
            int cnt = counts[be];
            const float* base = hs + (size_t)b * (S_ * D_) + k0base + part * 32;
            #pragma unroll
            for (int k = 0; k < K_; ++k) {
                if (k < cnt) {
                    int row = idx[be * K_ + k];
                    const float4* p = (const float4*)(base + (size_t)row * D_);
                    #pragma unroll
                    for (int j = 0; j < 8; ++j) {
                        float4 v = p[j];
                        a[j].x += v.x; a[j].y += v.y; a[j].z += v.z; a[j].w += v.w;
                    }
                }
            }
            float inv = 1.0f / (float)cnt;
            #pragma unroll
            for (int j = 0; j < 8; ++j) {
                a[j].x *= inv; a[j].y *= inv; a[j].z *= inv; a[j].w *= inv;
            }
        }
        // swizzled store: logical float4-col c4 = part*8+j -> c4 ^ (r&7)
        #pragma unroll
        for (int j = 0; j < 8; ++j) {
            int c4 = (part * 8 + j) ^ (r & 7);
            *(float4*)&sA[r * KCHUNK + c4 * 4] = a[j];
        }
    }

    int row0 = (tid >> 4) * 4;         // 0..60
    int col0 = (tid & 15) * 8;         // 0..120

    unsigned long long acc[4][4];
    #pragma unroll
    for (int i = 0; i < 4; ++i)
        #pragma unroll
        for (int p = 0; p < 4; ++p) acc[i][p] = 0ULL;

    // ---- Stage 2: GEMM over 4 BK tiles ----
    #pragma unroll 1
    for (int t4 = 0; t4 < KCHUNK / BK; ++t4) {
        __syncthreads();
        // W tile: 32 k x 128 cols = 1024 float4, 4 per thread (coalesced)
        #pragma unroll
        for (int it = 0; it < 4; ++it) {
            int i2 = it * 256 + tid;
            int kr = i2 >> 5;
            int cq = i2 & 31;
            float4 v = *(const float4*)(g_wt + (size_t)(k0base + t4 * BK + kr) * T_ + cq * 4);
            *(float4*)&sW[kr][cq * 4] = v;
        }
        __syncthreads();

        #pragma unroll
        for (int g = 0; g < BK / 4; ++g) {
            float4 rA[4];
            #pragma unroll
            for (int i = 0; i < 4; ++i) {
                int row = row0 + i;
                int c4 = (t4 * 8 + g) ^ (row & 7);
                rA[i] = *(const float4*)&sA[row * KCHUNK + c4 * 4];
            }
            #pragma unroll
            for (int j = 0; j < 4; ++j) {
                ulonglong2 w0 = *(const ulonglong2*)&sW[g * 4 + j][col0];
                ulonglong2 w1 = *(const ulonglong2*)&sW[g * 4 + j][col0 + 4];
                #pragma unroll
                for (int i = 0; i < 4; ++i) {
                    float aj = (j == 0) ? rA[i].x : (j == 1) ? rA[i].y
                             : (j == 2) ? rA[i].z : rA[i].w;
                    unsigned long long a2 = pack2(aj);
                    ffma2(acc[i][0], a2, w0.x);
                    ffma2(acc[i][1], a2, w0.y);
                    ffma2(acc[i][2], a2, w1.x);
                    ffma2(acc[i][3], a2, w1.y);
                }
            }
        }
    }

    float* outp = g_part + (size_t)split * (B_ * E_ * T_);
    #pragma unroll
    for (int i = 0; i < 4; ++i) {
        ulonglong2 v0, v1;
        v0.x = acc[i][0]; v0.y = acc[i][1];
        v1.x = acc[i][2]; v1.y = acc[i][3];
        size_t base = (size_t)(b * BM + row0 + i) * T_ + col0;
        *(ulonglong2*)(outp + base)     = v0;
        *(ulonglong2*)(outp + base + 4) = v1;
    }
}

// ---------------------------------------------------------------------------
// Kernel R: reduce 8 partials + bias -> out. Scalar per thread, high occupancy.
// ---------------------------------------------------------------------------
__global__ __launch_bounds__(256) void reduce_kernel(
    const float* __restrict__ bias, float* __restrict__ out)
{
    int i = blockIdx.x * 256 + threadIdx.x;   // 0 .. 262143
    float s = bias[i & (T_ - 1)];
    #pragma unroll
    for (int sp = 0; sp < NSPLIT; ++sp)
        s += g_part[(size_t)sp * (B_ * E_ * T_) + i];
    out[i] = s;
}

// ---------------------------------------------------------------------------
extern "C" void kernel_launch(void* const* d_in, const int* in_sizes, int n_in,
                              void* d_out, int out_size)
{
    const float* hs     = (const float*)d_in[0];
    const int*   idx    = (const int*)  d_in[1];
    const int*   counts = (const int*)  d_in[2];
    const int*   nent   = (const int*)  d_in[3];
    const float* fcw    = (const float*)d_in[4];
    const float* fcb    = (const float*)d_in[5];
    float*       out    = (float*)d_out;

    transpose_kernel<<<dim3(D_ / 32, T_ / 32), dim3(32, 8)>>>(fcw);
    gemm_fused<<<dim3(B_, NSPLIT), 256>>>(hs, idx, counts, nent);
    reduce_kernel<<<(B_ * E_ * T_) / 256, 256>>>(fcb, out);
}

// round 4
// speedup vs baseline: 1.0468x; 1.0468x over previous
#include <cuda_runtime.h>

#define B_ 32
#define S_ 2048
#define D_ 1024
#define E_ 64
#define K_ 8
#define T_ 128       // N_TAGS
#define NSPLIT 8
#define KCHUNK (D_ / NSPLIT)   // 128
#define BK 32
#define BM 64

// Scratch (allocation-free rule: __device__ globals)
__device__ float g_ent[B_ * E_ * D_];            // 8 MB pooled embeddings
__device__ float g_part[NSPLIT * B_ * E_ * T_];  // 8 MB k-split partials

// ---- packed f32x2 helpers (sm_103a) --------------------------------------
__device__ __forceinline__ unsigned long long pack2(float a) {
    unsigned long long r;
    asm("mov.b64 %0, {%1, %1};" : "=l"(r) : "f"(a));
    return r;
}
__device__ __forceinline__ void ffma2(unsigned long long& d,
                                      unsigned long long a,
                                      unsigned long long b) {
    asm("fma.rn.f32x2 %0, %1, %2, %3;" : "=l"(d) : "l"(a), "l"(b), "l"(d));
}

// ---------------------------------------------------------------------------
// Kernel P: gather + masked mean pool.
// grid=1024, block=256. Two entities per block; 128 threads x 8 floats each.
// Up to 16 independent LDG.128 in flight per thread.
// ---------------------------------------------------------------------------
__global__ __launch_bounds__(256) void pool_kernel(
    const float* __restrict__ hs,      // [B,S,D]
    const int*   __restrict__ idx,     // [B,E,K]
    const int*   __restrict__ counts,  // [B,E]
    const int*   __restrict__ nent)    // [B]
{
    int be   = blockIdx.x * 2 + (threadIdx.x >> 7);   // entity 0..2047
    int lane = threadIdx.x & 127;                      // 128 thr per entity
    int b    = be >> 6;
    int e    = be & 63;
    int cnt  = counts[be];
    bool active = (e < nent[b]);

    float4 a0 = make_float4(0.f, 0.f, 0.f, 0.f);
    float4 a1 = make_float4(0.f, 0.f, 0.f, 0.f);
    if (active) {
        const float* base = hs + (size_t)b * (S_ * D_) + lane * 8;
        #pragma unroll
        for (int k = 0; k < K_; ++k) {
            if (k < cnt) {
                int row = idx[be * K_ + k];
                const float4* p = (const float4*)(base + (size_t)row * D_);
                float4 v0 = p[0];
                float4 v1 = p[1];
                a0.x += v0.x; a0.y += v0.y; a0.z += v0.z; a0.w += v0.w;
                a1.x += v1.x; a1.y += v1.y; a1.z += v1.z; a1.w += v1.w;
            }
        }
        float inv = 1.0f / (float)cnt;
        a0.x *= inv; a0.y *= inv; a0.z *= inv; a0.w *= inv;
        a1.x *= inv; a1.y *= inv; a1.z *= inv; a1.w *= inv;
    }
    float4* o = (float4*)(g_ent + (size_t)be * D_ + lane * 8);
    o[0] = a0;
    o[1] = a1;
}

// ---------------------------------------------------------------------------
// Kernel B: k-split GEMM partials, fc_w loaded directly (transpose via SMEM).
// grid = (32 m-blocks, 8 k-splits), block = 256 threads.
// BM=64, BN=128, BK=32; per-thread 4 rows x 8 cols via f32x2 FMA.
// ---------------------------------------------------------------------------
__global__ __launch_bounds__(256) void gemm_kernel(
    const float* __restrict__ W)       // fc_w [T,D]
{
    __shared__ __align__(16) float sA[BM][36];    // [row][k]
    __shared__ __align__(16) float sW[BK][132];   // [k][col], 132 keeps 16B align

    int tid   = threadIdx.x;
    int mblk  = blockIdx.x;
    int split = blockIdx.y;
    int row0  = (tid >> 4) * 4;        // 0..60
    int col0  = (tid & 15) * 8;        // 0..120
    int k0base = split * KCHUNK;

    unsigned long long acc[4][4];
    #pragma unroll
    for (int i = 0; i < 4; ++i)
        #pragma unroll
        for (int p = 0; p < 4; ++p) acc[i][p] = 0ULL;

    #pragma unroll 1
    for (int t4 = 0; t4 < KCHUNK / BK; ++t4) {
        int k0 = k0base + t4 * BK;

        // A tile: 64 rows x 32 k = 512 float4, 2 per thread
        {
            int i0 = tid;
            int i1 = tid + 256;
            int r0 = i0 >> 3, kq0 = i0 & 7;
            int r1 = i1 >> 3, kq1 = i1 & 7;
            float4 v0 = *(const float4*)(g_ent + (size_t)(mblk * BM + r0) * D_ + k0 + kq0 * 4);
            float4 v1 = *(const float4*)(g_ent + (size_t)(mblk * BM + r1) * D_ + k0 + kq1 * 4);
            *(float4*)&sA[r0][kq0 * 4] = v0;
            *(float4*)&sA[r1][kq1 * 4] = v1;
        }
        // W tile: load fc_w[col][k0..k0+31] coalesced, store transposed.
        // 128 cols x 8 float4 = 1024 float4, 4 per thread.
        #pragma unroll
        for (int it = 0; it < 4; ++it) {
            int i2  = it * 256 + tid;
            int col = i2 >> 3;          // 0..127
            int q   = i2 & 7;           // 0..7 -> k = q*4..q*4+3
            float4 v = *(const float4*)(W + (size_t)col * D_ + k0 + q * 4);
            sW[q * 4 + 0][col] = v.x;
            sW[q * 4 + 1][col] = v.y;
            sW[q * 4 + 2][col] = v.z;
            sW[q * 4 + 3][col] = v.w;
        }
        __syncthreads();

        #pragma unroll
        for (int g = 0; g < BK / 4; ++g) {
            float4 rA[4];
            #pragma unroll
            for (int i = 0; i < 4; ++i)
                rA[i] = *(const float4*)&sA[row0 + i][g * 4];

            #pragma unroll
            for (int j = 0; j < 4; ++j) {
                ulonglong2 w0 = *(const ulonglong2*)&sW[g * 4 + j][col0];
                ulonglong2 w1 = *(const ulonglong2*)&sW[g * 4 + j][col0 + 4];
                #pragma unroll
                for (int i = 0; i < 4; ++i) {
                    float aj = (j == 0) ? rA[i].x : (j == 1) ? rA[i].y
                             : (j == 2) ? rA[i].z : rA[i].w;
                    unsigned long long a2 = pack2(aj);
                    ffma2(acc[i][0], a2, w0.x);
                    ffma2(acc[i][1], a2, w0.y);
                    ffma2(acc[i][2], a2, w1.x);
                    ffma2(acc[i][3], a2, w1.y);
                }
            }
        }
        __syncthreads();
    }

    float* outp = g_part + (size_t)split * (B_ * E_ * T_);
    #pragma unroll
    for (int i = 0; i < 4; ++i) {
        ulonglong2 v0, v1;
        v0.x = acc[i][0]; v0.y = acc[i][1];
        v1.x = acc[i][2]; v1.y = acc[i][3];
        size_t base = (size_t)(mblk * BM + row0 + i) * T_ + col0;
        *(ulonglong2*)(outp + base)     = v0;
        *(ulonglong2*)(outp + base + 4) = v1;
    }
}

// ---------------------------------------------------------------------------
// Kernel R: reduce 8 partials + bias -> out. Scalar per thread, high occupancy.
// ---------------------------------------------------------------------------
__global__ __launch_bounds__(256) void reduce_kernel(
    const float* __restrict__ bias, float* __restrict__ out)
{
    int i = blockIdx.x * 256 + threadIdx.x;   // 0 .. 262143
    float s = bias[i & (T_ - 1)];
    #pragma unroll
    for (int sp = 0; sp < NSPLIT; ++sp)
        s += g_part[(size_t)sp * (B_ * E_ * T_) + i];
    out[i] = s;
}

// ---------------------------------------------------------------------------
extern "C" void kernel_launch(void* const* d_in, const int* in_sizes, int n_in,
                              void* d_out, int out_size)
{
    const float* hs     = (const float*)d_in[0];
    const int*   idx    = (const int*)  d_in[1];
    const int*   counts = (const int*)  d_in[2];
    const int*   nent   = (const int*)  d_in[3];
    const float* fcw    = (const float*)d_in[4];
    const float* fcb    = (const float*)d_in[5];
    float*       out    = (float*)d_out;

    pool_kernel<<<B_ * E_ / 2, 256>>>(hs, idx, counts, nent);
    gemm_kernel<<<dim3(B_ * E_ / BM, NSPLIT), 256>>>(fcw);
    reduce_kernel<<<(B_ * E_ * T_) / 256, 256>>>(fcb, out);
}